// round 15
// baseline (speedup 1.0000x reference)
#include <cuda_runtime.h>
#include <cuda_bf16.h>
#include <cstdint>
#include <math.h>

#define H2   512
#define NB   8
#define TDEC 64
#define TENC 512
#define MDEC (NB*TDEC)   // 512
#define MENC (NB*TENC)   // 4096

// ---------------- scratch ----------------
__device__ float g_dp[MDEC*H2];
__device__ float g_ep[MENC*H2];
__device__ float g_mdp[MDEC];
__device__ float g_mep[MENC];
__device__ float g_Senc[NB*H2];
__device__ float g_partS[NB*16*H2];
__device__ float g_partC[NB*64*H2];
__device__ float g_split[256*2*128*8];   // split-K partials (2 MB)
__device__ int   g_cnt1[256];
__device__ int   g_cnt2[256];
__device__ __nv_bfloat16 g_enc_hi[MENC*H2];
__device__ __nv_bfloat16 g_enc_lo[MENC*H2];
__device__ __nv_bfloat16 g_encT_hi[MENC*H2];
__device__ __nv_bfloat16 g_encT_lo[MENC*H2];
__device__ __nv_bfloat16 g_dec_hi[MDEC*H2];
__device__ __nv_bfloat16 g_dec_lo[MDEC*H2];
__device__ __nv_bfloat16 g_We_hi[H2*H2];
__device__ __nv_bfloat16 g_We_lo[H2*H2];
__device__ __nv_bfloat16 g_Wd_hi[H2*H2];
__device__ __nv_bfloat16 g_Wd_lo[H2*H2];
__device__ __nv_bfloat16 g_Ahi[MDEC*H2];
__device__ __nv_bfloat16 g_Alo[MDEC*H2];
__device__ __nv_bfloat16 g_Ehi[MENC*H2];
__device__ __nv_bfloat16 g_Elo[MENC*H2];
__device__ __nv_bfloat16 g_Lhi[MDEC*TENC];
__device__ __nv_bfloat16 g_Llo[MDEC*TENC];

__device__ __forceinline__ uint32_t smem_to_u32(const void* p) {
    uint32_t a;
    asm("{ .reg .u64 tmp; cvta.to.shared.u64 tmp, %1; cvt.u32.u64 %0, tmp; }" : "=r"(a) : "l"(p));
    return a;
}

// ---------------- cp.async ----------------
#define CP_ASYNC16(s, g) asm volatile("cp.async.cg.shared.global [%0], [%1], 16;" :: "r"(s), "l"(g))
#define CP_COMMIT()      asm volatile("cp.async.commit_group;")
#define CP_WAIT0()       asm volatile("cp.async.wait_group 0;" ::: "memory")
#define CP_WAIT1()       asm volatile("cp.async.wait_group 1;" ::: "memory")

// ---------------- mma / ldmatrix ----------------
#define LDSM_X4(r0,r1,r2,r3,addr) \
    asm volatile("ldmatrix.sync.aligned.m8n8.x4.shared.b16 {%0,%1,%2,%3}, [%4];" \
        : "=r"(r0), "=r"(r1), "=r"(r2), "=r"(r3) : "r"(addr))

#define MMA_BF16(ac, a, b0, b1) \
    asm volatile("mma.sync.aligned.m16n8k16.row.col.f32.bf16.bf16.f32 " \
        "{%0,%1,%2,%3}, {%4,%5,%6,%7}, {%8,%9}, {%0,%1,%2,%3};" \
        : "+f"((ac)[0]), "+f"((ac)[1]), "+f"((ac)[2]), "+f"((ac)[3]) \
        : "r"((a)[0]), "r"((a)[1]), "r"((a)[2]), "r"((a)[3]), "r"(b0), "r"(b1))

// ---------------- hi/lo split ----------------
__device__ __forceinline__ void split2(float a, float b, uint32_t& hi, uint32_t& lo){
    __nv_bfloat16 ha = __float2bfloat16(a), hb = __float2bfloat16(b);
    __nv_bfloat16 la = __float2bfloat16(a - __bfloat162float(ha));
    __nv_bfloat16 lb = __float2bfloat16(b - __bfloat162float(hb));
    hi = ((uint32_t)__bfloat16_as_ushort(hb) << 16) | __bfloat16_as_ushort(ha);
    lo = ((uint32_t)__bfloat16_as_ushort(lb) << 16) | __bfloat16_as_ushort(la);
}
__device__ __forceinline__ void split1(float a, unsigned short& hi, unsigned short& lo){
    __nv_bfloat16 ha = __float2bfloat16(a);
    __nv_bfloat16 la = __float2bfloat16(a - __bfloat162float(ha));
    hi = __bfloat16_as_ushort(ha);
    lo = __bfloat16_as_ushort(la);
}

// ---------------------------------------------------------------------------
// conv_all: enc hi/lo + encT + partS; dec hi/lo; W hi/lo.
// ---------------------------------------------------------------------------
__global__ void __launch_bounds__(256) conv_all(
    const float* __restrict__ enc, const float* __restrict__ dec,
    const float* __restrict__ W,
    __nv_bfloat16* __restrict__ ehi, __nv_bfloat16* __restrict__ elo,
    __nv_bfloat16* __restrict__ ethi, __nv_bfloat16* __restrict__ etlo,
    __nv_bfloat16* __restrict__ dhi, __nv_bfloat16* __restrict__ dlo,
    __nv_bfloat16* __restrict__ wdhi, __nv_bfloat16* __restrict__ wdlo,
    __nv_bfloat16* __restrict__ wehi, __nv_bfloat16* __restrict__ welo,
    float* __restrict__ partS)
{
    const int bid = blockIdx.x;
    const int tid = threadIdx.x;
    if (bid < 2048) {
        __shared__ unsigned short sh[32][33], sl[32][33];
        __shared__ float ssum[8][32];
        const int b  = bid >> 8;
        const int jt = (bid >> 4) & 15;
        const int dT = (bid & 15) * 32;
        const int jT = jt * 32;
        const int x = tid & 31, y = tid >> 5;
        float csum = 0.f;
#pragma unroll
        for (int k = 0; k < 4; k++) {
            const int row = y + k*8;
            const long src = ((long)b*512 + jT + row)*512 + dT + x;
            float v = enc[src];
            csum += v;
            unsigned short h, l;
            split1(v, h, l);
            sh[row][x] = h; sl[row][x] = l;
            ((unsigned short*)ehi)[src] = h;
            ((unsigned short*)elo)[src] = l;
        }
        ssum[y][x] = csum;
        __syncthreads();
#pragma unroll
        for (int k = 0; k < 4; k++) {
            const int row = y + k*8;
            const long dst = ((long)b*512 + dT + row)*512 + jT + x;
            ((unsigned short*)ethi)[dst] = sh[x][row];
            ((unsigned short*)etlo)[dst] = sl[x][row];
        }
        if (y == 0) {
            float s = ssum[0][x];
#pragma unroll
            for (int w = 1; w < 8; w++) s += ssum[w][x];
            partS[((long)b*16 + jt)*512 + dT + x] = s;
        }
    } else if (bid < 2304) {
        const int i = (bid - 2048)*256 + tid;
        float4 v = ((const float4*)dec)[i];
        uint2 h, l;
        split2(v.x, v.y, h.x, l.x);
        split2(v.z, v.w, h.y, l.y);
        ((uint2*)dhi)[i] = h;
        ((uint2*)dlo)[i] = l;
    } else {
        const int i = (bid - 2304)*256 + tid;
        const int o = i >> 8, q = i & 255;
        float4 v = *(const float4*)(W + (long)o*1024 + q*4);
        uint2 h, l;
        split2(v.x, v.y, h.x, l.x);
        split2(v.z, v.w, h.y, l.y);
        const int c = q & 127;
        __nv_bfloat16* ph = (q < 128) ? wdhi : wehi;
        __nv_bfloat16* pl = (q < 128) ? wdlo : welo;
        ((uint2*)(ph + (long)o*512))[c] = h;
        ((uint2*)(pl + (long)o*512))[c] = l;
    }
}

// ---------------------------------------------------------------------------
// 128x128 HMMA GEMM (dual): blockIdx.y < 32 -> ep, else dp
// ---------------------------------------------------------------------------
#define ARR_PITCH 10240            // 128 rows * 80 B
#define BUF_PITCH (4*ARR_PITCH)
#define MMA_SMEM  (2*BUF_PITCH)    // 81920 B

__global__ void __launch_bounds__(256, 1) gemm_mma_dual(
    const __nv_bfloat16* __restrict__ eAhi, const __nv_bfloat16* __restrict__ eAlo,
    const __nv_bfloat16* __restrict__ eBhi, const __nv_bfloat16* __restrict__ eBlo,
    float* __restrict__ eC,
    const __nv_bfloat16* __restrict__ dAhi, const __nv_bfloat16* __restrict__ dAlo,
    const __nv_bfloat16* __restrict__ dBhi, const __nv_bfloat16* __restrict__ dBlo,
    float* __restrict__ dC)
{
    extern __shared__ char smem[];
    const uint32_t sb = smem_to_u32(smem);
    const int tid  = threadIdx.x;
    const int lane = tid & 31, wid = tid >> 5;
    const int warp_m = wid & 3, warp_n = wid >> 2;
    const bool isEp = blockIdx.y < 32;
    const int m0 = (isEp ? blockIdx.y : blockIdx.y - 32) * 128;
    const int n0 = blockIdx.x * 128;
    const __nv_bfloat16* Ahi = isEp ? eAhi : dAhi;
    const __nv_bfloat16* Alo = isEp ? eAlo : dAlo;
    const __nv_bfloat16* Bhi = isEp ? eBhi : dBhi;
    const __nv_bfloat16* Blo = isEp ? eBlo : dBlo;
    float* C = isEp ? eC : dC;

    const int ch0row = tid >> 2, ch0cc = (tid & 3);
    const int ch1row = (tid + 256) >> 2, ch1cc = ch0cc;
    const long gA0 = (long)(m0 + ch0row)*H2 + ch0cc*8;
    const long gA1 = (long)(m0 + ch1row)*H2 + ch1cc*8;
    const long gB0 = (long)(n0 + ch0row)*H2 + ch0cc*8;
    const long gB1 = (long)(n0 + ch1row)*H2 + ch1cc*8;
    const uint32_t s0 = ch0row*80 + ch0cc*16;
    const uint32_t s1 = ch1row*80 + ch1cc*16;

    const int lrow = lane & 15;
    const int lk   = (lane >> 4) * 8;
    uint32_t aOff[2], bOff[4];
#pragma unroll
    for (int t = 0; t < 2; t++)
        aOff[t] = (uint32_t)(((warp_m*32 + t*16 + lrow)*40 + lk)*2);
#pragma unroll
    for (int g = 0; g < 4; g++)
        bOff[g] = (uint32_t)(((warp_n*64 + g*16 + lrow)*40 + lk)*2);

    float acc[2][8][4];
#pragma unroll
    for (int t = 0; t < 2; t++)
#pragma unroll
        for (int n = 0; n < 8; n++)
#pragma unroll
            for (int q = 0; q < 4; q++) acc[t][n][q] = 0.f;

    {
        CP_ASYNC16(sb + s0,                (const char*)(Ahi + gA0));
        CP_ASYNC16(sb + s1,                (const char*)(Ahi + gA1));
        CP_ASYNC16(sb + ARR_PITCH   + s0,  (const char*)(Alo + gA0));
        CP_ASYNC16(sb + ARR_PITCH   + s1,  (const char*)(Alo + gA1));
        CP_ASYNC16(sb + 2*ARR_PITCH + s0,  (const char*)(Bhi + gB0));
        CP_ASYNC16(sb + 2*ARR_PITCH + s1,  (const char*)(Bhi + gB1));
        CP_ASYNC16(sb + 3*ARR_PITCH + s0,  (const char*)(Blo + gB0));
        CP_ASYNC16(sb + 3*ARR_PITCH + s1,  (const char*)(Blo + gB1));
        CP_COMMIT();
        CP_WAIT0();
    }
    __syncthreads();

    int buf = 0;
    for (int kc = 0; kc < 16; kc++) {
        const bool more = (kc + 1) < 16;
        if (more) {
            const uint32_t db = sb + (buf ^ 1)*BUF_PITCH;
            const long gk = (kc + 1)*32;
            CP_ASYNC16(db + s0,                (const char*)(Ahi + gA0 + gk));
            CP_ASYNC16(db + s1,                (const char*)(Ahi + gA1 + gk));
            CP_ASYNC16(db + ARR_PITCH   + s0,  (const char*)(Alo + gA0 + gk));
            CP_ASYNC16(db + ARR_PITCH   + s1,  (const char*)(Alo + gA1 + gk));
            CP_ASYNC16(db + 2*ARR_PITCH + s0,  (const char*)(Bhi + gB0 + gk));
            CP_ASYNC16(db + 2*ARR_PITCH + s1,  (const char*)(Bhi + gB1 + gk));
            CP_ASYNC16(db + 3*ARR_PITCH + s0,  (const char*)(Blo + gB0 + gk));
            CP_ASYNC16(db + 3*ARR_PITCH + s1,  (const char*)(Blo + gB1 + gk));
            CP_COMMIT();
        }
        const uint32_t cb = sb + buf*BUF_PITCH;
#pragma unroll
        for (int kk = 0; kk < 2; kk++) {
            const uint32_t ko = kk*32;
            uint32_t ah[2][4], al[2][4];
#pragma unroll
            for (int t = 0; t < 2; t++) {
                LDSM_X4(ah[t][0], ah[t][1], ah[t][2], ah[t][3], cb + aOff[t] + ko);
                LDSM_X4(al[t][0], al[t][1], al[t][2], al[t][3], cb + ARR_PITCH + aOff[t] + ko);
            }
#pragma unroll
            for (int g = 0; g < 4; g++) {
                uint32_t bh0, bh1, bh2, bh3, bl0, bl1, bl2, bl3;
                LDSM_X4(bh0, bh1, bh2, bh3, cb + 2*ARR_PITCH + bOff[g] + ko);
                LDSM_X4(bl0, bl1, bl2, bl3, cb + 3*ARR_PITCH + bOff[g] + ko);
#pragma unroll
                for (int t = 0; t < 2; t++) {
                    MMA_BF16(acc[t][2*g],   ah[t], bh0, bh2);
                    MMA_BF16(acc[t][2*g],   ah[t], bl0, bl2);
                    MMA_BF16(acc[t][2*g],   al[t], bh0, bh2);
                    MMA_BF16(acc[t][2*g+1], ah[t], bh1, bh3);
                    MMA_BF16(acc[t][2*g+1], ah[t], bl1, bl3);
                    MMA_BF16(acc[t][2*g+1], al[t], bh1, bh3);
                }
            }
        }
        if (more) {
            CP_WAIT0();
            __syncthreads();
            buf ^= 1;
        }
    }

    const int rbase = m0 + warp_m*32 + (lane >> 2);
    const int cbase = n0 + warp_n*64 + (lane & 3)*2;
#pragma unroll
    for (int t = 0; t < 2; t++) {
#pragma unroll
        for (int n = 0; n < 8; n++) {
            const int r = rbase + t*16;
            const int c = cbase + n*8;
            float2 v0; v0.x = acc[t][n][0]; v0.y = acc[t][n][1];
            float2 v1; v1.x = acc[t][n][2]; v1.y = acc[t][n][3];
            *(float2*)(C + (long)r*H2 + c)       = v0;
            *(float2*)(C + (long)(r + 8)*H2 + c) = v1;
        }
    }
}

// ---------------------------------------------------------------------------
// fused_mid: blocks 0..2303 = rowmax+exp (E then A); blocks 2304..3327 =
// colreduceC + Senc finalize; block 3328 zeroes the split-K counters.
// ---------------------------------------------------------------------------
__global__ void __launch_bounds__(256) fused_mid(
    const float* __restrict__ ep, const float* __restrict__ dp,
    const float* __restrict__ enc, const float* __restrict__ bias,
    __nv_bfloat16* __restrict__ Ehi, __nv_bfloat16* __restrict__ Elo, float* __restrict__ mep,
    __nv_bfloat16* __restrict__ Ahi, __nv_bfloat16* __restrict__ Alo, float* __restrict__ mdp,
    float* __restrict__ partC, const float* __restrict__ partS, float* __restrict__ Senc,
    int* __restrict__ cnt1, int* __restrict__ cnt2)
{
    const int bid = blockIdx.x;
    const int t = threadIdx.x;
    if (bid == 3328) {
        if (t < 256) { cnt1[t] = 0; cnt2[t] = 0; }
        return;
    }
    if (bid < 2304) {
        const int half = t >> 7;
        const int lane128 = t & 127;
        const bool isE = bid < 2048;
        const long r = (long)(isE ? bid : bid - 2048)*2 + half;
        const float* in = isE ? ep : dp;
        __nv_bfloat16* oh = isE ? Ehi : Ahi;
        __nv_bfloat16* ol = isE ? Elo : Alo;
        float* om = isE ? mep : mdp;

        float4 v = *(const float4*)(in + r*H2 + lane128*4);
        if (isE) {
            float4 bv = *(const float4*)(bias + lane128*4);
            v.x += bv.x; v.y += bv.y; v.z += bv.z; v.w += bv.w;
        }
        float m = fmaxf(fmaxf(v.x, v.y), fmaxf(v.z, v.w));
#pragma unroll
        for (int o = 16; o; o >>= 1) m = fmaxf(m, __shfl_xor_sync(0xffffffffu, m, o));
        __shared__ float sm[8];
        if ((t & 31) == 0) sm[t >> 5] = m;
        __syncthreads();
        const int wb = half*4;
        float M = fmaxf(fmaxf(sm[wb], sm[wb+1]), fmaxf(sm[wb+2], sm[wb+3]));
        float e0 = __expf(v.x - M), e1 = __expf(v.y - M);
        float e2 = __expf(v.z - M), e3 = __expf(v.w - M);
        uint2 h, l;
        split2(e0, e1, h.x, l.x);
        split2(e2, e3, h.y, l.y);
        ((uint2*)(oh + r*H2))[lane128] = h;
        ((uint2*)(ol + r*H2))[lane128] = l;
        if (lane128 == 0) om[r] = M;
    } else {
        const int bid2 = bid - 2304;        // 1024 blocks: db(1b) | b(3b) | js(6b)
        const int db = bid2 & 1;
        const int b  = (bid2 >> 1) & 7;
        const int js = bid2 >> 4;           // 0..63
        const int d  = db*256 + t;
        const float* e = enc + (long)b*TENC*H2 + (long)js*8*H2 + d;
        const float* p = ep  + (long)b*TENC*H2 + (long)js*8*H2 + d;
        float c = 0.f;
#pragma unroll
        for (int j = 0; j < 8; j++) c += p[(long)j*H2] * e[(long)j*H2];
        partC[((long)b*64 + js)*H2 + d] = c;
        if (js == 0) {
            float s = 0.f;
#pragma unroll
            for (int q = 0; q < 16; q++) s += partS[((long)b*16 + q)*H2 + d];
            Senc[(long)b*H2 + d] = s;
        }
    }
}

// ---------------------------------------------------------------------------
// 32x32 batched HMMA GEMM, split-K(2), K-chunk 64, 3-stage ring, 128 thr.
// Grid (16, 4, 8) = 512 CTAs; y bit0 = m-tile, bit1 = K-half (256 each).
// Last-arriving CTA of each tile combines partials (fixed order) + epilogue.
// EPI==1: v = mrow[gr] + mcol[bz*512+c] + log(acc) -> hi/lo bf16 out
// EPI==2: out = (dp+bias)*Senc + Cc(smem) - acc    -> fp32 out
// ---------------------------------------------------------------------------
#define APITCH  144                 // bytes per 64-col bf16 row (9x16B, odd)
#define A32ARR  (32*APITCH)         // 4608 per array
#define A64_HI  0
#define A64_LO  (1*A32ARR)
#define B64_HI  (2*A32ARR)
#define B64_LO  (3*A32ARR)
#define BUF64   (4*A32ARR)          // 18432 per stage
#define SMEM64  (3*BUF64)           // 55296

template<int EPI>
__global__ void __launch_bounds__(128) mma64(
    const __nv_bfloat16* __restrict__ Ahi, const __nv_bfloat16* __restrict__ Alo, long sA,
    const __nv_bfloat16* __restrict__ Bhi, const __nv_bfloat16* __restrict__ Blo, long sB,
    const float* __restrict__ mrow, const float* __restrict__ mcol,
    __nv_bfloat16* __restrict__ oHi, __nv_bfloat16* __restrict__ oLo,
    const float* __restrict__ dp, const float* __restrict__ bias,
    const float* __restrict__ Senc, const float* __restrict__ partC,
    float* __restrict__ out,
    float* __restrict__ part, int* __restrict__ cnt)
{
    extern __shared__ char smem[];
    __shared__ float sCc4[4][32];
    __shared__ float sCc[32];
    __shared__ int lastFlag;
    const uint32_t sb = smem_to_u32(smem);
    const int tid  = threadIdx.x;
    const int lane = tid & 31, wid = tid >> 5;
    const int warp_m = wid & 1, warp_n = wid >> 1;   // 2 x 2, warp tile 16x16
    const int bz = blockIdx.z;
    const int mt = blockIdx.y & 1;
    const int kh = blockIdx.y >> 1;
    const int m0 = mt * 32;
    const int n0 = blockIdx.x * 32;
    const int tileLin = (bz*2 + mt)*16 + blockIdx.x;   // 0..255

    const __nv_bfloat16* Ah = Ahi + (long)bz*sA + (long)m0*H2 + kh*256;
    const __nv_bfloat16* Al = Alo + (long)bz*sA + (long)m0*H2 + kh*256;
    const __nv_bfloat16* Bh = Bhi + (long)bz*sB + kh*256;
    const __nv_bfloat16* Bl = Blo + (long)bz*sB + kh*256;

    // loads: 32 rows x 128B per array per chunk; thread -> row=tid>>2, 2x16B
    const int rowA = tid >> 2, cc = tid & 3;
    const long gA = (long)rowA*H2 + cc*8;
    const long gB = (long)(n0 + rowA)*H2 + cc*8;
    const uint32_t sOff  = rowA*APITCH + cc*16;
    const uint32_t sOff2 = sOff + 64;

    const int lrow = lane & 15;
    const int lk   = (lane >> 4) * 8;
    const uint32_t aOff = (uint32_t)(((warp_m*16 + lrow)*72 + lk)*2);
    const uint32_t bOff = (uint32_t)(((warp_n*16 + lrow)*72 + lk)*2);

    float acc[2][4];
#pragma unroll
    for (int n = 0; n < 2; n++)
#pragma unroll
        for (int q = 0; q < 4; q++) acc[n][q] = 0.f;

    // prologue: issue chunks 0,1 into stages 0,1
#pragma unroll
    for (int pc = 0; pc < 2; pc++) {
        const uint32_t db = sb + pc*BUF64;
        const long gk = (long)pc*64;
        CP_ASYNC16(db + A64_HI + sOff,  (const char*)(Ah + gA + gk));
        CP_ASYNC16(db + A64_HI + sOff2, (const char*)(Ah + gA + gk + 32));
        CP_ASYNC16(db + A64_LO + sOff,  (const char*)(Al + gA + gk));
        CP_ASYNC16(db + A64_LO + sOff2, (const char*)(Al + gA + gk + 32));
        CP_ASYNC16(db + B64_HI + sOff,  (const char*)(Bh + gB + gk));
        CP_ASYNC16(db + B64_HI + sOff2, (const char*)(Bh + gB + gk + 32));
        CP_ASYNC16(db + B64_LO + sOff,  (const char*)(Bl + gB + gk));
        CP_ASYNC16(db + B64_LO + sOff2, (const char*)(Bl + gB + gk + 32));
        CP_COMMIT();
    }
    // overlap: partial Cc sums (4 threads per column, 16 partials each)
    if (EPI == 2) {
        const int c = tid & 31, q = tid >> 5;
        float s = 0.f;
#pragma unroll
        for (int js = 0; js < 16; js++)
            s += partC[((long)bz*64 + q*16 + js)*H2 + n0 + c];
        sCc4[q][c] = s;
    }
    __syncthreads();
    if (EPI == 2 && tid < 32)
        sCc[tid] = sCc4[0][tid] + sCc4[1][tid] + sCc4[2][tid] + sCc4[3][tid];

    for (int kc = 0; kc < 4; kc++) {
        if (kc < 3) { CP_WAIT1(); } else { CP_WAIT0(); }
        __syncthreads();
        if (kc + 2 < 4) {
            const uint32_t db = sb + ((kc + 2) % 3)*BUF64;
            const long gk = (long)(kc + 2)*64;
            CP_ASYNC16(db + A64_HI + sOff,  (const char*)(Ah + gA + gk));
            CP_ASYNC16(db + A64_HI + sOff2, (const char*)(Ah + gA + gk + 32));
            CP_ASYNC16(db + A64_LO + sOff,  (const char*)(Al + gA + gk));
            CP_ASYNC16(db + A64_LO + sOff2, (const char*)(Al + gA + gk + 32));
            CP_ASYNC16(db + B64_HI + sOff,  (const char*)(Bh + gB + gk));
            CP_ASYNC16(db + B64_HI + sOff2, (const char*)(Bh + gB + gk + 32));
            CP_ASYNC16(db + B64_LO + sOff,  (const char*)(Bl + gB + gk));
            CP_ASYNC16(db + B64_LO + sOff2, (const char*)(Bl + gB + gk + 32));
            CP_COMMIT();
        }
        const uint32_t cb = sb + (kc % 3)*BUF64;
#pragma unroll
        for (int kk = 0; kk < 4; kk++) {
            const uint32_t ko = kk*32;   // 16 cols * 2B
            uint32_t ah[4], al[4];
            LDSM_X4(ah[0], ah[1], ah[2], ah[3], cb + A64_HI + aOff + ko);
            LDSM_X4(al[0], al[1], al[2], al[3], cb + A64_LO + aOff + ko);
            uint32_t bh0, bh1, bh2, bh3, bl0, bl1, bl2, bl3;
            LDSM_X4(bh0, bh1, bh2, bh3, cb + B64_HI + bOff + ko);
            LDSM_X4(bl0, bl1, bl2, bl3, cb + B64_LO + bOff + ko);
            MMA_BF16(acc[0], ah, bh0, bh2);
            MMA_BF16(acc[1], ah, bh1, bh3);
            MMA_BF16(acc[0], ah, bl0, bl2);
            MMA_BF16(acc[1], ah, bl1, bl3);
            MMA_BF16(acc[0], al, bh0, bh2);
            MMA_BF16(acc[1], al, bh1, bh3);
        }
    }

    // store this half's partial (fp32)
    float* pp = part + (((long)tileLin*2 + kh)*128 + tid)*8;
#pragma unroll
    for (int n = 0; n < 2; n++)
#pragma unroll
        for (int q = 0; q < 4; q++) pp[n*4 + q] = acc[n][q];
    __threadfence();
    __syncthreads();
    if (tid == 0) lastFlag = (atomicAdd(&cnt[tileLin], 1) == 1);
    __syncthreads();
    if (!lastFlag) return;
    __threadfence();

    // last CTA: combine in fixed order p0 + p1
    {
        const float* p0 = part + (((long)tileLin*2 + 0)*128 + tid)*8;
        const float* p1 = part + (((long)tileLin*2 + 1)*128 + tid)*8;
#pragma unroll
        for (int n = 0; n < 2; n++)
#pragma unroll
            for (int q = 0; q < 4; q++)
                acc[n][q] = p0[n*4 + q] + p1[n*4 + q];
    }

    const int rbase = warp_m*16 + (lane >> 2);
    const int cbase = n0 + warp_n*16 + (lane & 3)*2;
#pragma unroll
    for (int n = 0; n < 2; n++) {
#pragma unroll
        for (int h = 0; h < 2; h++) {
            const int r  = rbase + h*8;
            const int gr = bz*TDEC + m0 + r;
            const int c  = cbase + n*8;
            const float a0 = acc[n][2*h], a1 = acc[n][2*h+1];
            if (EPI == 1) {
                float mr = mrow[gr];
                float v0 = mr + mcol[(long)bz*TENC + c]     + __logf(a0);
                float v1 = mr + mcol[(long)bz*TENC + c + 1] + __logf(a1);
                uint32_t hh, ll;
                split2(v0, v1, hh, ll);
                *(uint32_t*)(oHi + (long)gr*TENC + c) = hh;
                *(uint32_t*)(oLo + (long)gr*TENC + c) = ll;
            } else {
                const long ib = (long)bz*H2 + c;
                float o0 = (dp[(long)gr*H2 + c]   + bias[c])   * Senc[ib]   + sCc[c - n0]     - a0;
                float o1 = (dp[(long)gr*H2 + c+1] + bias[c+1]) * Senc[ib+1] + sCc[c - n0 + 1] - a1;
                float2 ov; ov.x = o0; ov.y = o1;
                *(float2*)(out + (long)gr*H2 + c) = ov;
            }
        }
    }
}

// ---------------------------------------------------------------------------
extern "C" void kernel_launch(void* const* d_in, const int* in_sizes, int n_in,
                              void* d_out, int out_size)
{
    const float* enc  = (const float*)d_in[0];
    const float* dec  = (const float*)d_in[1];
    const float* W    = (const float*)d_in[2];
    const float* bias = (const float*)d_in[3];
    float* out = (float*)d_out;

    float *dp, *ep, *mdp, *mep, *Senc, *pS, *pC, *spl;
    int *c1, *c2;
    __nv_bfloat16 *ehi, *elo, *ethi, *etlo, *dhi, *dlo, *wehi, *welo, *wdhi, *wdlo;
    __nv_bfloat16 *Ahi, *Alo, *Ehi, *Elo, *Lhi, *Llo;
    cudaGetSymbolAddress((void**)&dp,   g_dp);
    cudaGetSymbolAddress((void**)&ep,   g_ep);
    cudaGetSymbolAddress((void**)&mdp,  g_mdp);
    cudaGetSymbolAddress((void**)&mep,  g_mep);
    cudaGetSymbolAddress((void**)&Senc, g_Senc);
    cudaGetSymbolAddress((void**)&pS,   g_partS);
    cudaGetSymbolAddress((void**)&pC,   g_partC);
    cudaGetSymbolAddress((void**)&spl,  g_split);
    cudaGetSymbolAddress((void**)&c1,   g_cnt1);
    cudaGetSymbolAddress((void**)&c2,   g_cnt2);
    cudaGetSymbolAddress((void**)&ehi,  g_enc_hi);
    cudaGetSymbolAddress((void**)&elo,  g_enc_lo);
    cudaGetSymbolAddress((void**)&ethi, g_encT_hi);
    cudaGetSymbolAddress((void**)&etlo, g_encT_lo);
    cudaGetSymbolAddress((void**)&dhi,  g_dec_hi);
    cudaGetSymbolAddress((void**)&dlo,  g_dec_lo);
    cudaGetSymbolAddress((void**)&wehi, g_We_hi);
    cudaGetSymbolAddress((void**)&welo, g_We_lo);
    cudaGetSymbolAddress((void**)&wdhi, g_Wd_hi);
    cudaGetSymbolAddress((void**)&wdlo, g_Wd_lo);
    cudaGetSymbolAddress((void**)&Ahi,  g_Ahi);
    cudaGetSymbolAddress((void**)&Alo,  g_Alo);
    cudaGetSymbolAddress((void**)&Ehi,  g_Ehi);
    cudaGetSymbolAddress((void**)&Elo,  g_Elo);
    cudaGetSymbolAddress((void**)&Lhi,  g_Lhi);
    cudaGetSymbolAddress((void**)&Llo,  g_Llo);

    cudaFuncSetAttribute(gemm_mma_dual, cudaFuncAttributeMaxDynamicSharedMemorySize, MMA_SMEM);
    cudaFuncSetAttribute(mma64<1>, cudaFuncAttributeMaxDynamicSharedMemorySize, SMEM64);
    cudaFuncSetAttribute(mma64<2>, cudaFuncAttributeMaxDynamicSharedMemorySize, SMEM64);

    // 0: all conversions + encT + partS
    conv_all<<<2816, 256>>>(enc, dec, W, ehi, elo, ethi, etlo,
                            dhi, dlo, wdhi, wdlo, wehi, welo, pS);
    // 1: ep + dp GEMMs
    gemm_mma_dual<<<dim3(4, 36), 256, MMA_SMEM>>>(
        ehi, elo, wehi, welo, ep, dhi, dlo, wdhi, wdlo, dp);
    // 2: rowmax+exp (E, A) + colreduceC + Senc finalize + counter reset
    fused_mid<<<3329, 256>>>(ep, dp, enc, bias, Ehi, Elo, mep,
                             Ahi, Alo, mdp, pC, pS, Senc, c1, c2);
    // 3: L = mdp + mep + log(A @ E^T) -> hi/lo  (512 CTAs, split-K)
    mma64<1><<<dim3(16, 4, NB), 128, SMEM64>>>(
        Ahi, Alo, (long)TDEC*H2, Ehi, Elo, (long)TENC*H2,
        mdp, mep, Lhi, Llo, nullptr, nullptr, nullptr, nullptr, nullptr,
        spl, c1);
    // 4: context = (dp+bias)*Senc + Cc - L @ enc  (512 CTAs, split-K)
    mma64<2><<<dim3(16, 4, NB), 128, SMEM64>>>(
        Lhi, Llo, (long)TDEC*TENC, ethi, etlo, (long)H2*TENC,
        nullptr, nullptr, nullptr, nullptr, dp, bias, Senc, pC, out,
        spl, c2);
}

// round 16
// speedup vs baseline: 1.1768x; 1.1768x over previous
#include <cuda_runtime.h>
#include <cuda_bf16.h>
#include <cstdint>
#include <math.h>

#define H2   512
#define NB   8
#define TDEC 64
#define TENC 512
#define MDEC (NB*TDEC)   // 512
#define MENC (NB*TENC)   // 4096

// ---------------- scratch ----------------
__device__ float g_dp[MDEC*H2];
__device__ float g_ep[MENC*H2];
__device__ float g_mdp[MDEC];
__device__ float g_mep[MENC];
__device__ float g_Senc[NB*H2];
__device__ float g_partS[NB*16*H2];
__device__ float g_partC[NB*64*H2];
__device__ __nv_bfloat16 g_enc_hi[MENC*H2];
__device__ __nv_bfloat16 g_enc_lo[MENC*H2];
__device__ __nv_bfloat16 g_encT_hi[MENC*H2];
__device__ __nv_bfloat16 g_encT_lo[MENC*H2];
__device__ __nv_bfloat16 g_dec_hi[MDEC*H2];
__device__ __nv_bfloat16 g_dec_lo[MDEC*H2];
__device__ __nv_bfloat16 g_We_hi[H2*H2];
__device__ __nv_bfloat16 g_We_lo[H2*H2];
__device__ __nv_bfloat16 g_Wd_hi[H2*H2];
__device__ __nv_bfloat16 g_Wd_lo[H2*H2];
__device__ __nv_bfloat16 g_Ahi[MDEC*H2];
__device__ __nv_bfloat16 g_Ehi[MENC*H2];
__device__ __nv_bfloat16 g_Elo[MENC*H2];
__device__ __nv_bfloat16 g_Lhi[MDEC*TENC];
__device__ __nv_bfloat16 g_Llo[MDEC*TENC];

__device__ __forceinline__ uint32_t smem_to_u32(const void* p) {
    uint32_t a;
    asm("{ .reg .u64 tmp; cvta.to.shared.u64 tmp, %1; cvt.u32.u64 %0, tmp; }" : "=r"(a) : "l"(p));
    return a;
}

// ---------------- cp.async ----------------
#define CP_ASYNC16(s, g) asm volatile("cp.async.cg.shared.global [%0], [%1], 16;" :: "r"(s), "l"(g))
#define CP_COMMIT()      asm volatile("cp.async.commit_group;")
#define CP_WAIT0()       asm volatile("cp.async.wait_group 0;" ::: "memory")
#define CP_WAIT1()       asm volatile("cp.async.wait_group 1;" ::: "memory")
#define CP_WAIT2()       asm volatile("cp.async.wait_group 2;" ::: "memory")

// ---------------- mma / ldmatrix ----------------
#define LDSM_X4(r0,r1,r2,r3,addr) \
    asm volatile("ldmatrix.sync.aligned.m8n8.x4.shared.b16 {%0,%1,%2,%3}, [%4];" \
        : "=r"(r0), "=r"(r1), "=r"(r2), "=r"(r3) : "r"(addr))

#define MMA_BF16(ac, a, b0, b1) \
    asm volatile("mma.sync.aligned.m16n8k16.row.col.f32.bf16.bf16.f32 " \
        "{%0,%1,%2,%3}, {%4,%5,%6,%7}, {%8,%9}, {%0,%1,%2,%3};" \
        : "+f"((ac)[0]), "+f"((ac)[1]), "+f"((ac)[2]), "+f"((ac)[3]) \
        : "r"((a)[0]), "r"((a)[1]), "r"((a)[2]), "r"((a)[3]), "r"(b0), "r"(b1))

// ---------------- hi/lo split ----------------
__device__ __forceinline__ void split2(float a, float b, uint32_t& hi, uint32_t& lo){
    __nv_bfloat16 ha = __float2bfloat16(a), hb = __float2bfloat16(b);
    __nv_bfloat16 la = __float2bfloat16(a - __bfloat162float(ha));
    __nv_bfloat16 lb = __float2bfloat16(b - __bfloat162float(hb));
    hi = ((uint32_t)__bfloat16_as_ushort(hb) << 16) | __bfloat16_as_ushort(ha);
    lo = ((uint32_t)__bfloat16_as_ushort(lb) << 16) | __bfloat16_as_ushort(la);
}
__device__ __forceinline__ void split1(float a, unsigned short& hi, unsigned short& lo){
    __nv_bfloat16 ha = __float2bfloat16(a);
    __nv_bfloat16 la = __float2bfloat16(a - __bfloat162float(ha));
    hi = __bfloat16_as_ushort(ha);
    lo = __bfloat16_as_ushort(la);
}

// ---------------------------------------------------------------------------
// conv_all: enc hi/lo + encT + partS; dec hi/lo; W hi/lo.
// ---------------------------------------------------------------------------
__global__ void __launch_bounds__(256) conv_all(
    const float* __restrict__ enc, const float* __restrict__ dec,
    const float* __restrict__ W,
    __nv_bfloat16* __restrict__ ehi, __nv_bfloat16* __restrict__ elo,
    __nv_bfloat16* __restrict__ ethi, __nv_bfloat16* __restrict__ etlo,
    __nv_bfloat16* __restrict__ dhi, __nv_bfloat16* __restrict__ dlo,
    __nv_bfloat16* __restrict__ wdhi, __nv_bfloat16* __restrict__ wdlo,
    __nv_bfloat16* __restrict__ wehi, __nv_bfloat16* __restrict__ welo,
    float* __restrict__ partS)
{
    const int bid = blockIdx.x;
    const int tid = threadIdx.x;
    if (bid < 2048) {
        __shared__ unsigned short sh[32][33], sl[32][33];
        __shared__ float ssum[8][32];
        const int b  = bid >> 8;
        const int jt = (bid >> 4) & 15;
        const int dT = (bid & 15) * 32;
        const int jT = jt * 32;
        const int x = tid & 31, y = tid >> 5;
        float csum = 0.f;
#pragma unroll
        for (int k = 0; k < 4; k++) {
            const int row = y + k*8;
            const long src = ((long)b*512 + jT + row)*512 + dT + x;
            float v = enc[src];
            csum += v;
            unsigned short h, l;
            split1(v, h, l);
            sh[row][x] = h; sl[row][x] = l;
            ((unsigned short*)ehi)[src] = h;
            ((unsigned short*)elo)[src] = l;
        }
        ssum[y][x] = csum;
        __syncthreads();
#pragma unroll
        for (int k = 0; k < 4; k++) {
            const int row = y + k*8;
            const long dst = ((long)b*512 + dT + row)*512 + jT + x;
            ((unsigned short*)ethi)[dst] = sh[x][row];
            ((unsigned short*)etlo)[dst] = sl[x][row];
        }
        if (y == 0) {
            float s = ssum[0][x];
#pragma unroll
            for (int w = 1; w < 8; w++) s += ssum[w][x];
            partS[((long)b*16 + jt)*512 + dT + x] = s;
        }
    } else if (bid < 2304) {
        const int i = (bid - 2048)*256 + tid;
        float4 v = ((const float4*)dec)[i];
        uint2 h, l;
        split2(v.x, v.y, h.x, l.x);
        split2(v.z, v.w, h.y, l.y);
        ((uint2*)dhi)[i] = h;
        ((uint2*)dlo)[i] = l;
    } else {
        const int i = (bid - 2304)*256 + tid;
        const int o = i >> 8, q = i & 255;
        float4 v = *(const float4*)(W + (long)o*1024 + q*4);
        uint2 h, l;
        split2(v.x, v.y, h.x, l.x);
        split2(v.z, v.w, h.y, l.y);
        const int c = q & 127;
        __nv_bfloat16* ph = (q < 128) ? wdhi : wehi;
        __nv_bfloat16* pl = (q < 128) ? wdlo : welo;
        ((uint2*)(ph + (long)o*512))[c] = h;
        ((uint2*)(pl + (long)o*512))[c] = l;
    }
}

// ---------------------------------------------------------------------------
// 128x128 HMMA GEMM (dual): blockIdx.y < 32 -> ep, else dp
// ---------------------------------------------------------------------------
#define ARR_PITCH 10240            // 128 rows * 80 B
#define BUF_PITCH (4*ARR_PITCH)
#define MMA_SMEM  (2*BUF_PITCH)    // 81920 B

__global__ void __launch_bounds__(256, 1) gemm_mma_dual(
    const __nv_bfloat16* __restrict__ eAhi, const __nv_bfloat16* __restrict__ eAlo,
    const __nv_bfloat16* __restrict__ eBhi, const __nv_bfloat16* __restrict__ eBlo,
    float* __restrict__ eC,
    const __nv_bfloat16* __restrict__ dAhi, const __nv_bfloat16* __restrict__ dAlo,
    const __nv_bfloat16* __restrict__ dBhi, const __nv_bfloat16* __restrict__ dBlo,
    float* __restrict__ dC)
{
    extern __shared__ char smem[];
    const uint32_t sb = smem_to_u32(smem);
    const int tid  = threadIdx.x;
    const int lane = tid & 31, wid = tid >> 5;
    const int warp_m = wid & 3, warp_n = wid >> 2;
    const bool isEp = blockIdx.y < 32;
    const int m0 = (isEp ? blockIdx.y : blockIdx.y - 32) * 128;
    const int n0 = blockIdx.x * 128;
    const __nv_bfloat16* Ahi = isEp ? eAhi : dAhi;
    const __nv_bfloat16* Alo = isEp ? eAlo : dAlo;
    const __nv_bfloat16* Bhi = isEp ? eBhi : dBhi;
    const __nv_bfloat16* Blo = isEp ? eBlo : dBlo;
    float* C = isEp ? eC : dC;

    const int ch0row = tid >> 2, ch0cc = (tid & 3);
    const int ch1row = (tid + 256) >> 2, ch1cc = ch0cc;
    const long gA0 = (long)(m0 + ch0row)*H2 + ch0cc*8;
    const long gA1 = (long)(m0 + ch1row)*H2 + ch1cc*8;
    const long gB0 = (long)(n0 + ch0row)*H2 + ch0cc*8;
    const long gB1 = (long)(n0 + ch1row)*H2 + ch1cc*8;
    const uint32_t s0 = ch0row*80 + ch0cc*16;
    const uint32_t s1 = ch1row*80 + ch1cc*16;

    const int lrow = lane & 15;
    const int lk   = (lane >> 4) * 8;
    uint32_t aOff[2], bOff[4];
#pragma unroll
    for (int t = 0; t < 2; t++)
        aOff[t] = (uint32_t)(((warp_m*32 + t*16 + lrow)*40 + lk)*2);
#pragma unroll
    for (int g = 0; g < 4; g++)
        bOff[g] = (uint32_t)(((warp_n*64 + g*16 + lrow)*40 + lk)*2);

    float acc[2][8][4];
#pragma unroll
    for (int t = 0; t < 2; t++)
#pragma unroll
        for (int n = 0; n < 8; n++)
#pragma unroll
            for (int q = 0; q < 4; q++) acc[t][n][q] = 0.f;

    {
        CP_ASYNC16(sb + s0,                (const char*)(Ahi + gA0));
        CP_ASYNC16(sb + s1,                (const char*)(Ahi + gA1));
        CP_ASYNC16(sb + ARR_PITCH   + s0,  (const char*)(Alo + gA0));
        CP_ASYNC16(sb + ARR_PITCH   + s1,  (const char*)(Alo + gA1));
        CP_ASYNC16(sb + 2*ARR_PITCH + s0,  (const char*)(Bhi + gB0));
        CP_ASYNC16(sb + 2*ARR_PITCH + s1,  (const char*)(Bhi + gB1));
        CP_ASYNC16(sb + 3*ARR_PITCH + s0,  (const char*)(Blo + gB0));
        CP_ASYNC16(sb + 3*ARR_PITCH + s1,  (const char*)(Blo + gB1));
        CP_COMMIT();
        CP_WAIT0();
    }
    __syncthreads();

    int buf = 0;
    for (int kc = 0; kc < 16; kc++) {
        const bool more = (kc + 1) < 16;
        if (more) {
            const uint32_t db = sb + (buf ^ 1)*BUF_PITCH;
            const long gk = (kc + 1)*32;
            CP_ASYNC16(db + s0,                (const char*)(Ahi + gA0 + gk));
            CP_ASYNC16(db + s1,                (const char*)(Ahi + gA1 + gk));
            CP_ASYNC16(db + ARR_PITCH   + s0,  (const char*)(Alo + gA0 + gk));
            CP_ASYNC16(db + ARR_PITCH   + s1,  (const char*)(Alo + gA1 + gk));
            CP_ASYNC16(db + 2*ARR_PITCH + s0,  (const char*)(Bhi + gB0 + gk));
            CP_ASYNC16(db + 2*ARR_PITCH + s1,  (const char*)(Bhi + gB1 + gk));
            CP_ASYNC16(db + 3*ARR_PITCH + s0,  (const char*)(Blo + gB0 + gk));
            CP_ASYNC16(db + 3*ARR_PITCH + s1,  (const char*)(Blo + gB1 + gk));
            CP_COMMIT();
        }
        const uint32_t cb = sb + buf*BUF_PITCH;
#pragma unroll
        for (int kk = 0; kk < 2; kk++) {
            const uint32_t ko = kk*32;
            uint32_t ah[2][4], al[2][4];
#pragma unroll
            for (int t = 0; t < 2; t++) {
                LDSM_X4(ah[t][0], ah[t][1], ah[t][2], ah[t][3], cb + aOff[t] + ko);
                LDSM_X4(al[t][0], al[t][1], al[t][2], al[t][3], cb + ARR_PITCH + aOff[t] + ko);
            }
#pragma unroll
            for (int g = 0; g < 4; g++) {
                uint32_t bh0, bh1, bh2, bh3, bl0, bl1, bl2, bl3;
                LDSM_X4(bh0, bh1, bh2, bh3, cb + 2*ARR_PITCH + bOff[g] + ko);
                LDSM_X4(bl0, bl1, bl2, bl3, cb + 3*ARR_PITCH + bOff[g] + ko);
#pragma unroll
                for (int t = 0; t < 2; t++) {
                    MMA_BF16(acc[t][2*g],   ah[t], bh0, bh2);
                    MMA_BF16(acc[t][2*g],   ah[t], bl0, bl2);
                    MMA_BF16(acc[t][2*g],   al[t], bh0, bh2);
                    MMA_BF16(acc[t][2*g+1], ah[t], bh1, bh3);
                    MMA_BF16(acc[t][2*g+1], ah[t], bl1, bl3);
                    MMA_BF16(acc[t][2*g+1], al[t], bh1, bh3);
                }
            }
        }
        if (more) {
            CP_WAIT0();
            __syncthreads();
            buf ^= 1;
        }
    }

    const int rbase = m0 + warp_m*32 + (lane >> 2);
    const int cbase = n0 + warp_n*64 + (lane & 3)*2;
#pragma unroll
    for (int t = 0; t < 2; t++) {
#pragma unroll
        for (int n = 0; n < 8; n++) {
            const int r = rbase + t*16;
            const int c = cbase + n*8;
            float2 v0; v0.x = acc[t][n][0]; v0.y = acc[t][n][1];
            float2 v1; v1.x = acc[t][n][2]; v1.y = acc[t][n][3];
            *(float2*)(C + (long)r*H2 + c)       = v0;
            *(float2*)(C + (long)(r + 8)*H2 + c) = v1;
        }
    }
}

// ---------------------------------------------------------------------------
// fused_mid: blocks 0..2303 = rowmax+exp (E then A); blocks 2304..3327 =
// colreduceC (64 j-splits of 8 rows) + Senc finalize on js==0.
// E written hi/lo; A written hi only (mma64<1> uses single-bf16 A).
// ---------------------------------------------------------------------------
__global__ void __launch_bounds__(256) fused_mid(
    const float* __restrict__ ep, const float* __restrict__ dp,
    const float* __restrict__ enc, const float* __restrict__ bias,
    __nv_bfloat16* __restrict__ Ehi, __nv_bfloat16* __restrict__ Elo, float* __restrict__ mep,
    __nv_bfloat16* __restrict__ Ahi, float* __restrict__ mdp,
    float* __restrict__ partC, const float* __restrict__ partS, float* __restrict__ Senc)
{
    const int bid = blockIdx.x;
    const int t = threadIdx.x;
    if (bid < 2304) {
        const int half = t >> 7;
        const int lane128 = t & 127;
        const bool isE = bid < 2048;
        const long r = (long)(isE ? bid : bid - 2048)*2 + half;
        const float* in = isE ? ep : dp;
        float* om = isE ? mep : mdp;

        float4 v = *(const float4*)(in + r*H2 + lane128*4);
        if (isE) {
            float4 bv = *(const float4*)(bias + lane128*4);
            v.x += bv.x; v.y += bv.y; v.z += bv.z; v.w += bv.w;
        }
        float m = fmaxf(fmaxf(v.x, v.y), fmaxf(v.z, v.w));
#pragma unroll
        for (int o = 16; o; o >>= 1) m = fmaxf(m, __shfl_xor_sync(0xffffffffu, m, o));
        __shared__ float sm[8];
        if ((t & 31) == 0) sm[t >> 5] = m;
        __syncthreads();
        const int wb = half*4;
        float M = fmaxf(fmaxf(sm[wb], sm[wb+1]), fmaxf(sm[wb+2], sm[wb+3]));
        float e0 = __expf(v.x - M), e1 = __expf(v.y - M);
        float e2 = __expf(v.z - M), e3 = __expf(v.w - M);
        uint2 h, l;
        split2(e0, e1, h.x, l.x);
        split2(e2, e3, h.y, l.y);
        if (isE) {
            ((uint2*)(Ehi + r*H2))[lane128] = h;
            ((uint2*)(Elo + r*H2))[lane128] = l;
        } else {
            ((uint2*)(Ahi + r*H2))[lane128] = h;
        }
        if (lane128 == 0) om[r] = M;
    } else {
        const int bid2 = bid - 2304;        // 1024 blocks: db(1b) | b(3b) | js(6b)
        const int db = bid2 & 1;
        const int b  = (bid2 >> 1) & 7;
        const int js = bid2 >> 4;           // 0..63
        const int d  = db*256 + t;
        const float* e = enc + (long)b*TENC*H2 + (long)js*8*H2 + d;
        const float* p = ep  + (long)b*TENC*H2 + (long)js*8*H2 + d;
        float c = 0.f;
#pragma unroll
        for (int j = 0; j < 8; j++) c += p[(long)j*H2] * e[(long)j*H2];
        partC[((long)b*64 + js)*H2 + d] = c;
        if (js == 0) {
            float s = 0.f;
#pragma unroll
            for (int q = 0; q < 16; q++) s += partS[((long)b*16 + q)*H2 + d];
            Senc[(long)b*H2 + d] = s;
        }
    }
}

// ---------------------------------------------------------------------------
// 32x32 batched HMMA GEMM, K-chunk 64, 4-stage cp.async ring, 128 threads.
// Grid (16, 2, 8) = 256 CTAs. C = A*B^T per batch (bz), K=512.
// EPI==1: A single-bf16 (Ahi only), B hi/lo -> 2 MMA terms; 3 smem arrays.
//         v = mrow[gr] + mcol[bz*512+c] + log(acc) -> hi/lo bf16 out
// EPI==2: A hi/lo, B hi/lo -> 3 MMA terms; 4 smem arrays.
//         out = (dp+bias)*Senc + Cc(smem) - acc    -> fp32 out
// ---------------------------------------------------------------------------
#define APITCH  144                 // bytes per 64-col bf16 row (9x16B, odd)
#define A32ARR  (32*APITCH)         // 4608 per array
#define SMEM64_1 (4*(3*A32ARR))     // 55296
#define SMEM64_2 (4*(4*A32ARR))     // 73728

template<int EPI>
__global__ void __launch_bounds__(128) mma64(
    const __nv_bfloat16* __restrict__ Ahi, const __nv_bfloat16* __restrict__ Alo, long sA,
    const __nv_bfloat16* __restrict__ Bhi, const __nv_bfloat16* __restrict__ Blo, long sB,
    const float* __restrict__ mrow, const float* __restrict__ mcol,
    __nv_bfloat16* __restrict__ oHi, __nv_bfloat16* __restrict__ oLo,
    const float* __restrict__ dp, const float* __restrict__ bias,
    const float* __restrict__ Senc, const float* __restrict__ partC,
    float* __restrict__ out)
{
    constexpr int ARRS  = (EPI == 1) ? 3 : 4;
    constexpr int MO_AHI = 0;
    constexpr int MO_ALO = A32ARR;                       // EPI2 only
    constexpr int MO_BHI = ((EPI == 1) ? 1 : 2) * A32ARR;
    constexpr int MO_BLO = MO_BHI + A32ARR;
    constexpr int BUFSZ  = ARRS * A32ARR;

    extern __shared__ char smem[];
    __shared__ float sCc4[4][32];
    __shared__ float sCc[32];
    const uint32_t sb = smem_to_u32(smem);
    const int tid  = threadIdx.x;
    const int lane = tid & 31, wid = tid >> 5;
    const int warp_m = wid & 1, warp_n = wid >> 1;   // 2 x 2, warp tile 16x16
    const int bz = blockIdx.z;
    const int m0 = blockIdx.y * 32;
    const int n0 = blockIdx.x * 32;

    const __nv_bfloat16* Ah = Ahi + (long)bz*sA + (long)m0*H2;
    const __nv_bfloat16* Al = (EPI == 2) ? (Alo + (long)bz*sA + (long)m0*H2) : nullptr;
    const __nv_bfloat16* Bh = Bhi + (long)bz*sB;
    const __nv_bfloat16* Bl = Blo + (long)bz*sB;

    // loads: 32 rows x 128B per array per chunk; thread -> row=tid>>2, 2x16B
    const int rowA = tid >> 2, cc = tid & 3;
    const long gA = (long)rowA*H2 + cc*8;            // + kc*64 (+32 for 2nd)
    const long gB = (long)(n0 + rowA)*H2 + cc*8;
    const uint32_t sOff  = rowA*APITCH + cc*16;
    const uint32_t sOff2 = sOff + 64;

    const int lrow = lane & 15;
    const int lk   = (lane >> 4) * 8;
    const uint32_t aOff = (uint32_t)(((warp_m*16 + lrow)*72 + lk)*2);
    const uint32_t bOff = (uint32_t)(((warp_n*16 + lrow)*72 + lk)*2);

    float acc[2][4];
#pragma unroll
    for (int n = 0; n < 2; n++)
#pragma unroll
        for (int q = 0; q < 4; q++) acc[n][q] = 0.f;

    // prologue: issue chunks 0,1,2 into stages 0,1,2
#pragma unroll
    for (int pc = 0; pc < 3; pc++) {
        const uint32_t db = sb + pc*BUFSZ;
        const long gk = (long)pc*64;
        CP_ASYNC16(db + MO_AHI + sOff,  (const char*)(Ah + gA + gk));
        CP_ASYNC16(db + MO_AHI + sOff2, (const char*)(Ah + gA + gk + 32));
        if (EPI == 2) {
            CP_ASYNC16(db + MO_ALO + sOff,  (const char*)(Al + gA + gk));
            CP_ASYNC16(db + MO_ALO + sOff2, (const char*)(Al + gA + gk + 32));
        }
        CP_ASYNC16(db + MO_BHI + sOff,  (const char*)(Bh + gB + gk));
        CP_ASYNC16(db + MO_BHI + sOff2, (const char*)(Bh + gB + gk + 32));
        CP_ASYNC16(db + MO_BLO + sOff,  (const char*)(Bl + gB + gk));
        CP_ASYNC16(db + MO_BLO + sOff2, (const char*)(Bl + gB + gk + 32));
        CP_COMMIT();
    }
    // overlap: partial Cc sums (4 threads per column, 16 partials each)
    if (EPI == 2) {
        const int c = tid & 31, q = tid >> 5;
        float s = 0.f;
#pragma unroll
        for (int js = 0; js < 16; js++)
            s += partC[((long)bz*64 + q*16 + js)*H2 + n0 + c];
        sCc4[q][c] = s;
    }
    __syncthreads();
    if (EPI == 2 && tid < 32)
        sCc[tid] = sCc4[0][tid] + sCc4[1][tid] + sCc4[2][tid] + sCc4[3][tid];

    for (int kc = 0; kc < 8; kc++) {
        if (kc < 6)       { CP_WAIT2(); }
        else if (kc == 6) { CP_WAIT1(); }
        else              { CP_WAIT0(); }
        __syncthreads();
        if (kc + 3 < 8) {
            const uint32_t db = sb + ((kc + 3) & 3)*BUFSZ;
            const long gk = (long)(kc + 3)*64;
            CP_ASYNC16(db + MO_AHI + sOff,  (const char*)(Ah + gA + gk));
            CP_ASYNC16(db + MO_AHI + sOff2, (const char*)(Ah + gA + gk + 32));
            if (EPI == 2) {
                CP_ASYNC16(db + MO_ALO + sOff,  (const char*)(Al + gA + gk));
                CP_ASYNC16(db + MO_ALO + sOff2, (const char*)(Al + gA + gk + 32));
            }
            CP_ASYNC16(db + MO_BHI + sOff,  (const char*)(Bh + gB + gk));
            CP_ASYNC16(db + MO_BHI + sOff2, (const char*)(Bh + gB + gk + 32));
            CP_ASYNC16(db + MO_BLO + sOff,  (const char*)(Bl + gB + gk));
            CP_ASYNC16(db + MO_BLO + sOff2, (const char*)(Bl + gB + gk + 32));
            CP_COMMIT();
        }
        const uint32_t cb = sb + (kc & 3)*BUFSZ;
#pragma unroll
        for (int kk = 0; kk < 4; kk++) {
            const uint32_t ko = kk*32;   // 16 cols * 2B
            uint32_t ah[4];
            LDSM_X4(ah[0], ah[1], ah[2], ah[3], cb + MO_AHI + aOff + ko);
            uint32_t bh0, bh1, bh2, bh3, bl0, bl1, bl2, bl3;
            LDSM_X4(bh0, bh1, bh2, bh3, cb + MO_BHI + bOff + ko);
            LDSM_X4(bl0, bl1, bl2, bl3, cb + MO_BLO + bOff + ko);
            MMA_BF16(acc[0], ah, bh0, bh2);
            MMA_BF16(acc[1], ah, bh1, bh3);
            MMA_BF16(acc[0], ah, bl0, bl2);
            MMA_BF16(acc[1], ah, bl1, bl3);
            if (EPI == 2) {
                uint32_t al[4];
                LDSM_X4(al[0], al[1], al[2], al[3], cb + MO_ALO + aOff + ko);
                MMA_BF16(acc[0], al, bh0, bh2);
                MMA_BF16(acc[1], al, bh1, bh3);
            }
        }
    }

    const int rbase = warp_m*16 + (lane >> 2);
    const int cbase = n0 + warp_n*16 + (lane & 3)*2;
#pragma unroll
    for (int n = 0; n < 2; n++) {
#pragma unroll
        for (int h = 0; h < 2; h++) {
            const int r  = rbase + h*8;
            const int gr = bz*TDEC + m0 + r;
            const int c  = cbase + n*8;
            const float a0 = acc[n][2*h], a1 = acc[n][2*h+1];
            if (EPI == 1) {
                float mr = mrow[gr];
                float v0 = mr + mcol[(long)bz*TENC + c]     + __logf(a0);
                float v1 = mr + mcol[(long)bz*TENC + c + 1] + __logf(a1);
                uint32_t hh, ll;
                split2(v0, v1, hh, ll);
                *(uint32_t*)(oHi + (long)gr*TENC + c) = hh;
                *(uint32_t*)(oLo + (long)gr*TENC + c) = ll;
            } else {
                const long ib = (long)bz*H2 + c;
                float o0 = (dp[(long)gr*H2 + c]   + bias[c])   * Senc[ib]   + sCc[c - n0]     - a0;
                float o1 = (dp[(long)gr*H2 + c+1] + bias[c+1]) * Senc[ib+1] + sCc[c - n0 + 1] - a1;
                float2 ov; ov.x = o0; ov.y = o1;
                *(float2*)(out + (long)gr*H2 + c) = ov;
            }
        }
    }
}

// ---------------------------------------------------------------------------
extern "C" void kernel_launch(void* const* d_in, const int* in_sizes, int n_in,
                              void* d_out, int out_size)
{
    const float* enc  = (const float*)d_in[0];
    const float* dec  = (const float*)d_in[1];
    const float* W    = (const float*)d_in[2];
    const float* bias = (const float*)d_in[3];
    float* out = (float*)d_out;

    float *dp, *ep, *mdp, *mep, *Senc, *pS, *pC;
    __nv_bfloat16 *ehi, *elo, *ethi, *etlo, *dhi, *dlo, *wehi, *welo, *wdhi, *wdlo;
    __nv_bfloat16 *Ahi, *Ehi, *Elo, *Lhi, *Llo;
    cudaGetSymbolAddress((void**)&dp,   g_dp);
    cudaGetSymbolAddress((void**)&ep,   g_ep);
    cudaGetSymbolAddress((void**)&mdp,  g_mdp);
    cudaGetSymbolAddress((void**)&mep,  g_mep);
    cudaGetSymbolAddress((void**)&Senc, g_Senc);
    cudaGetSymbolAddress((void**)&pS,   g_partS);
    cudaGetSymbolAddress((void**)&pC,   g_partC);
    cudaGetSymbolAddress((void**)&ehi,  g_enc_hi);
    cudaGetSymbolAddress((void**)&elo,  g_enc_lo);
    cudaGetSymbolAddress((void**)&ethi, g_encT_hi);
    cudaGetSymbolAddress((void**)&etlo, g_encT_lo);
    cudaGetSymbolAddress((void**)&dhi,  g_dec_hi);
    cudaGetSymbolAddress((void**)&dlo,  g_dec_lo);
    cudaGetSymbolAddress((void**)&wehi, g_We_hi);
    cudaGetSymbolAddress((void**)&welo, g_We_lo);
    cudaGetSymbolAddress((void**)&wdhi, g_Wd_hi);
    cudaGetSymbolAddress((void**)&wdlo, g_Wd_lo);
    cudaGetSymbolAddress((void**)&Ahi,  g_Ahi);
    cudaGetSymbolAddress((void**)&Ehi,  g_Ehi);
    cudaGetSymbolAddress((void**)&Elo,  g_Elo);
    cudaGetSymbolAddress((void**)&Lhi,  g_Lhi);
    cudaGetSymbolAddress((void**)&Llo,  g_Llo);

    cudaFuncSetAttribute(gemm_mma_dual, cudaFuncAttributeMaxDynamicSharedMemorySize, MMA_SMEM);
    cudaFuncSetAttribute(mma64<1>, cudaFuncAttributeMaxDynamicSharedMemorySize, SMEM64_1);
    cudaFuncSetAttribute(mma64<2>, cudaFuncAttributeMaxDynamicSharedMemorySize, SMEM64_2);

    // 0: all conversions + encT + partS
    conv_all<<<2816, 256>>>(enc, dec, W, ehi, elo, ethi, etlo,
                            dhi, dlo, wdhi, wdlo, wehi, welo, pS);
    // 1: ep + dp GEMMs
    gemm_mma_dual<<<dim3(4, 36), 256, MMA_SMEM>>>(
        ehi, elo, wehi, welo, ep, dhi, dlo, wdhi, wdlo, dp);
    // 2: rowmax+exp (E hi/lo, A hi-only) + colreduceC + Senc finalize
    fused_mid<<<3328, 256>>>(ep, dp, enc, bias, Ehi, Elo, mep,
                             Ahi, mdp, pC, pS, Senc);
    // 3: L = mdp + mep + log(A @ E^T) -> hi/lo  (256 CTAs, 2-term)
    mma64<1><<<dim3(16, 2, NB), 128, SMEM64_1>>>(
        Ahi, nullptr, (long)TDEC*H2, Ehi, Elo, (long)TENC*H2,
        mdp, mep, Lhi, Llo, nullptr, nullptr, nullptr, nullptr, nullptr);
    // 4: context = (dp+bias)*Senc + Cc - L @ enc  (256 CTAs, 3-term)
    mma64<2><<<dim3(16, 2, NB), 128, SMEM64_2>>>(
        Lhi, Llo, (long)TDEC*TENC, ethi, etlo, (long)H2*TENC,
        nullptr, nullptr, nullptr, nullptr, dp, bias, Senc, pC, out);
}

// round 17
// speedup vs baseline: 1.2152x; 1.0326x over previous
#include <cuda_runtime.h>
#include <cuda_bf16.h>
#include <cstdint>
#include <math.h>

#define H2   512
#define NB   8
#define TDEC 64
#define TENC 512
#define MDEC (NB*TDEC)   // 512
#define MENC (NB*TENC)   // 4096

// ---------------- scratch ----------------
__device__ float g_dp[MDEC*H2];
__device__ float g_ep[MENC*H2];
__device__ float g_mdp[MDEC];
__device__ float g_mep[MENC];
__device__ float g_Senc[NB*H2];
__device__ float g_partS[NB*16*H2];
__device__ float g_partC[NB*64*H2];
__device__ __nv_bfloat16 g_enc_hi[MENC*H2];
__device__ __nv_bfloat16 g_enc_lo[MENC*H2];
__device__ __nv_bfloat16 g_encT_hi[MENC*H2];
__device__ __nv_bfloat16 g_encT_lo[MENC*H2];
__device__ __nv_bfloat16 g_dec_hi[MDEC*H2];
__device__ __nv_bfloat16 g_dec_lo[MDEC*H2];
__device__ __nv_bfloat16 g_We_hi[H2*H2];
__device__ __nv_bfloat16 g_We_lo[H2*H2];
__device__ __nv_bfloat16 g_Wd_hi[H2*H2];
__device__ __nv_bfloat16 g_Wd_lo[H2*H2];
__device__ __nv_bfloat16 g_Ahi[MDEC*H2];
__device__ __nv_bfloat16 g_Ehi[MENC*H2];
__device__ __nv_bfloat16 g_Lhi[MDEC*TENC];
__device__ __nv_bfloat16 g_Llo[MDEC*TENC];

__device__ __forceinline__ uint32_t smem_to_u32(const void* p) {
    uint32_t a;
    asm("{ .reg .u64 tmp; cvta.to.shared.u64 tmp, %1; cvt.u32.u64 %0, tmp; }" : "=r"(a) : "l"(p));
    return a;
}

// ---------------- cp.async ----------------
#define CP_ASYNC16(s, g) asm volatile("cp.async.cg.shared.global [%0], [%1], 16;" :: "r"(s), "l"(g))
#define CP_COMMIT()      asm volatile("cp.async.commit_group;")
#define CP_WAIT0()       asm volatile("cp.async.wait_group 0;" ::: "memory")
#define CP_WAIT1()       asm volatile("cp.async.wait_group 1;" ::: "memory")
#define CP_WAIT2()       asm volatile("cp.async.wait_group 2;" ::: "memory")

// ---------------- mma / ldmatrix ----------------
#define LDSM_X4(r0,r1,r2,r3,addr) \
    asm volatile("ldmatrix.sync.aligned.m8n8.x4.shared.b16 {%0,%1,%2,%3}, [%4];" \
        : "=r"(r0), "=r"(r1), "=r"(r2), "=r"(r3) : "r"(addr))

#define MMA_BF16(ac, a, b0, b1) \
    asm volatile("mma.sync.aligned.m16n8k16.row.col.f32.bf16.bf16.f32 " \
        "{%0,%1,%2,%3}, {%4,%5,%6,%7}, {%8,%9}, {%0,%1,%2,%3};" \
        : "+f"((ac)[0]), "+f"((ac)[1]), "+f"((ac)[2]), "+f"((ac)[3]) \
        : "r"((a)[0]), "r"((a)[1]), "r"((a)[2]), "r"((a)[3]), "r"(b0), "r"(b1))

// ---------------- hi/lo split ----------------
__device__ __forceinline__ void split2(float a, float b, uint32_t& hi, uint32_t& lo){
    __nv_bfloat16 ha = __float2bfloat16(a), hb = __float2bfloat16(b);
    __nv_bfloat16 la = __float2bfloat16(a - __bfloat162float(ha));
    __nv_bfloat16 lb = __float2bfloat16(b - __bfloat162float(hb));
    hi = ((uint32_t)__bfloat16_as_ushort(hb) << 16) | __bfloat16_as_ushort(ha);
    lo = ((uint32_t)__bfloat16_as_ushort(lb) << 16) | __bfloat16_as_ushort(la);
}
__device__ __forceinline__ void split1(float a, unsigned short& hi, unsigned short& lo){
    __nv_bfloat16 ha = __float2bfloat16(a);
    __nv_bfloat16 la = __float2bfloat16(a - __bfloat162float(ha));
    hi = __bfloat16_as_ushort(ha);
    lo = __bfloat16_as_ushort(la);
}
__device__ __forceinline__ uint32_t pack_hi2(float a, float b){
    __nv_bfloat16 ha = __float2bfloat16(a), hb = __float2bfloat16(b);
    return ((uint32_t)__bfloat16_as_ushort(hb) << 16) | __bfloat16_as_ushort(ha);
}

// ---------------------------------------------------------------------------
// conv_all: enc hi/lo + encT + partS; dec hi/lo; W hi/lo.
// ---------------------------------------------------------------------------
__global__ void __launch_bounds__(256) conv_all(
    const float* __restrict__ enc, const float* __restrict__ dec,
    const float* __restrict__ W,
    __nv_bfloat16* __restrict__ ehi, __nv_bfloat16* __restrict__ elo,
    __nv_bfloat16* __restrict__ ethi, __nv_bfloat16* __restrict__ etlo,
    __nv_bfloat16* __restrict__ dhi, __nv_bfloat16* __restrict__ dlo,
    __nv_bfloat16* __restrict__ wdhi, __nv_bfloat16* __restrict__ wdlo,
    __nv_bfloat16* __restrict__ wehi, __nv_bfloat16* __restrict__ welo,
    float* __restrict__ partS)
{
    const int bid = blockIdx.x;
    const int tid = threadIdx.x;
    if (bid < 2048) {
        __shared__ unsigned short sh[32][33], sl[32][33];
        __shared__ float ssum[8][32];
        const int b  = bid >> 8;
        const int jt = (bid >> 4) & 15;
        const int dT = (bid & 15) * 32;
        const int jT = jt * 32;
        const int x = tid & 31, y = tid >> 5;
        float csum = 0.f;
#pragma unroll
        for (int k = 0; k < 4; k++) {
            const int row = y + k*8;
            const long src = ((long)b*512 + jT + row)*512 + dT + x;
            float v = enc[src];
            csum += v;
            unsigned short h, l;
            split1(v, h, l);
            sh[row][x] = h; sl[row][x] = l;
            ((unsigned short*)ehi)[src] = h;
            ((unsigned short*)elo)[src] = l;
        }
        ssum[y][x] = csum;
        __syncthreads();
#pragma unroll
        for (int k = 0; k < 4; k++) {
            const int row = y + k*8;
            const long dst = ((long)b*512 + dT + row)*512 + jT + x;
            ((unsigned short*)ethi)[dst] = sh[x][row];
            ((unsigned short*)etlo)[dst] = sl[x][row];
        }
        if (y == 0) {
            float s = ssum[0][x];
#pragma unroll
            for (int w = 1; w < 8; w++) s += ssum[w][x];
            partS[((long)b*16 + jt)*512 + dT + x] = s;
        }
    } else if (bid < 2304) {
        const int i = (bid - 2048)*256 + tid;
        float4 v = ((const float4*)dec)[i];
        uint2 h, l;
        split2(v.x, v.y, h.x, l.x);
        split2(v.z, v.w, h.y, l.y);
        ((uint2*)dhi)[i] = h;
        ((uint2*)dlo)[i] = l;
    } else {
        const int i = (bid - 2304)*256 + tid;
        const int o = i >> 8, q = i & 255;
        float4 v = *(const float4*)(W + (long)o*1024 + q*4);
        uint2 h, l;
        split2(v.x, v.y, h.x, l.x);
        split2(v.z, v.w, h.y, l.y);
        const int c = q & 127;
        __nv_bfloat16* ph = (q < 128) ? wdhi : wehi;
        __nv_bfloat16* pl = (q < 128) ? wdlo : welo;
        ((uint2*)(ph + (long)o*512))[c] = h;
        ((uint2*)(pl + (long)o*512))[c] = l;
    }
}

// ---------------------------------------------------------------------------
// 128x128 HMMA GEMM (dual): blockIdx.y < 32 -> ep, else dp
// ---------------------------------------------------------------------------
#define ARR_PITCH 10240            // 128 rows * 80 B
#define BUF_PITCH (4*ARR_PITCH)
#define MMA_SMEM  (2*BUF_PITCH)    // 81920 B

__global__ void __launch_bounds__(256, 1) gemm_mma_dual(
    const __nv_bfloat16* __restrict__ eAhi, const __nv_bfloat16* __restrict__ eAlo,
    const __nv_bfloat16* __restrict__ eBhi, const __nv_bfloat16* __restrict__ eBlo,
    float* __restrict__ eC,
    const __nv_bfloat16* __restrict__ dAhi, const __nv_bfloat16* __restrict__ dAlo,
    const __nv_bfloat16* __restrict__ dBhi, const __nv_bfloat16* __restrict__ dBlo,
    float* __restrict__ dC)
{
    extern __shared__ char smem[];
    const uint32_t sb = smem_to_u32(smem);
    const int tid  = threadIdx.x;
    const int lane = tid & 31, wid = tid >> 5;
    const int warp_m = wid & 3, warp_n = wid >> 2;
    const bool isEp = blockIdx.y < 32;
    const int m0 = (isEp ? blockIdx.y : blockIdx.y - 32) * 128;
    const int n0 = blockIdx.x * 128;
    const __nv_bfloat16* Ahi = isEp ? eAhi : dAhi;
    const __nv_bfloat16* Alo = isEp ? eAlo : dAlo;
    const __nv_bfloat16* Bhi = isEp ? eBhi : dBhi;
    const __nv_bfloat16* Blo = isEp ? eBlo : dBlo;
    float* C = isEp ? eC : dC;

    const int ch0row = tid >> 2, ch0cc = (tid & 3);
    const int ch1row = (tid + 256) >> 2, ch1cc = ch0cc;
    const long gA0 = (long)(m0 + ch0row)*H2 + ch0cc*8;
    const long gA1 = (long)(m0 + ch1row)*H2 + ch1cc*8;
    const long gB0 = (long)(n0 + ch0row)*H2 + ch0cc*8;
    const long gB1 = (long)(n0 + ch1row)*H2 + ch1cc*8;
    const uint32_t s0 = ch0row*80 + ch0cc*16;
    const uint32_t s1 = ch1row*80 + ch1cc*16;

    const int lrow = lane & 15;
    const int lk   = (lane >> 4) * 8;
    uint32_t aOff[2], bOff[4];
#pragma unroll
    for (int t = 0; t < 2; t++)
        aOff[t] = (uint32_t)(((warp_m*32 + t*16 + lrow)*40 + lk)*2);
#pragma unroll
    for (int g = 0; g < 4; g++)
        bOff[g] = (uint32_t)(((warp_n*64 + g*16 + lrow)*40 + lk)*2);

    float acc[2][8][4];
#pragma unroll
    for (int t = 0; t < 2; t++)
#pragma unroll
        for (int n = 0; n < 8; n++)
#pragma unroll
            for (int q = 0; q < 4; q++) acc[t][n][q] = 0.f;

    {
        CP_ASYNC16(sb + s0,                (const char*)(Ahi + gA0));
        CP_ASYNC16(sb + s1,                (const char*)(Ahi + gA1));
        CP_ASYNC16(sb + ARR_PITCH   + s0,  (const char*)(Alo + gA0));
        CP_ASYNC16(sb + ARR_PITCH   + s1,  (const char*)(Alo + gA1));
        CP_ASYNC16(sb + 2*ARR_PITCH + s0,  (const char*)(Bhi + gB0));
        CP_ASYNC16(sb + 2*ARR_PITCH + s1,  (const char*)(Bhi + gB1));
        CP_ASYNC16(sb + 3*ARR_PITCH + s0,  (const char*)(Blo + gB0));
        CP_ASYNC16(sb + 3*ARR_PITCH + s1,  (const char*)(Blo + gB1));
        CP_COMMIT();
        CP_WAIT0();
    }
    __syncthreads();

    int buf = 0;
    for (int kc = 0; kc < 16; kc++) {
        const bool more = (kc + 1) < 16;
        if (more) {
            const uint32_t db = sb + (buf ^ 1)*BUF_PITCH;
            const long gk = (kc + 1)*32;
            CP_ASYNC16(db + s0,                (const char*)(Ahi + gA0 + gk));
            CP_ASYNC16(db + s1,                (const char*)(Ahi + gA1 + gk));
            CP_ASYNC16(db + ARR_PITCH   + s0,  (const char*)(Alo + gA0 + gk));
            CP_ASYNC16(db + ARR_PITCH   + s1,  (const char*)(Alo + gA1 + gk));
            CP_ASYNC16(db + 2*ARR_PITCH + s0,  (const char*)(Bhi + gB0 + gk));
            CP_ASYNC16(db + 2*ARR_PITCH + s1,  (const char*)(Bhi + gB1 + gk));
            CP_ASYNC16(db + 3*ARR_PITCH + s0,  (const char*)(Blo + gB0 + gk));
            CP_ASYNC16(db + 3*ARR_PITCH + s1,  (const char*)(Blo + gB1 + gk));
            CP_COMMIT();
        }
        const uint32_t cb = sb + buf*BUF_PITCH;
#pragma unroll
        for (int kk = 0; kk < 2; kk++) {
            const uint32_t ko = kk*32;
            uint32_t ah[2][4], al[2][4];
#pragma unroll
            for (int t = 0; t < 2; t++) {
                LDSM_X4(ah[t][0], ah[t][1], ah[t][2], ah[t][3], cb + aOff[t] + ko);
                LDSM_X4(al[t][0], al[t][1], al[t][2], al[t][3], cb + ARR_PITCH + aOff[t] + ko);
            }
#pragma unroll
            for (int g = 0; g < 4; g++) {
                uint32_t bh0, bh1, bh2, bh3, bl0, bl1, bl2, bl3;
                LDSM_X4(bh0, bh1, bh2, bh3, cb + 2*ARR_PITCH + bOff[g] + ko);
                LDSM_X4(bl0, bl1, bl2, bl3, cb + 3*ARR_PITCH + bOff[g] + ko);
#pragma unroll
                for (int t = 0; t < 2; t++) {
                    MMA_BF16(acc[t][2*g],   ah[t], bh0, bh2);
                    MMA_BF16(acc[t][2*g],   ah[t], bl0, bl2);
                    MMA_BF16(acc[t][2*g],   al[t], bh0, bh2);
                    MMA_BF16(acc[t][2*g+1], ah[t], bh1, bh3);
                    MMA_BF16(acc[t][2*g+1], ah[t], bl1, bl3);
                    MMA_BF16(acc[t][2*g+1], al[t], bh1, bh3);
                }
            }
        }
        if (more) {
            CP_WAIT0();
            __syncthreads();
            buf ^= 1;
        }
    }

    const int rbase = m0 + warp_m*32 + (lane >> 2);
    const int cbase = n0 + warp_n*64 + (lane & 3)*2;
#pragma unroll
    for (int t = 0; t < 2; t++) {
#pragma unroll
        for (int n = 0; n < 8; n++) {
            const int r = rbase + t*16;
            const int c = cbase + n*8;
            float2 v0; v0.x = acc[t][n][0]; v0.y = acc[t][n][1];
            float2 v1; v1.x = acc[t][n][2]; v1.y = acc[t][n][3];
            *(float2*)(C + (long)r*H2 + c)       = v0;
            *(float2*)(C + (long)(r + 8)*H2 + c) = v1;
        }
    }
}

// ---------------------------------------------------------------------------
// fused_mid: blocks 0..2303 = rowmax+exp (E then A, hi only); blocks
// 2304..3327 = colreduceC (64 j-splits of 8 rows) + Senc finalize on js==0.
// ---------------------------------------------------------------------------
__global__ void __launch_bounds__(256) fused_mid(
    const float* __restrict__ ep, const float* __restrict__ dp,
    const float* __restrict__ enc, const float* __restrict__ bias,
    __nv_bfloat16* __restrict__ Ehi, float* __restrict__ mep,
    __nv_bfloat16* __restrict__ Ahi, float* __restrict__ mdp,
    float* __restrict__ partC, const float* __restrict__ partS, float* __restrict__ Senc)
{
    const int bid = blockIdx.x;
    const int t = threadIdx.x;
    if (bid < 2304) {
        const int half = t >> 7;
        const int lane128 = t & 127;
        const bool isE = bid < 2048;
        const long r = (long)(isE ? bid : bid - 2048)*2 + half;
        const float* in = isE ? ep : dp;
        __nv_bfloat16* oh = isE ? Ehi : Ahi;
        float* om = isE ? mep : mdp;

        float4 v = *(const float4*)(in + r*H2 + lane128*4);
        if (isE) {
            float4 bv = *(const float4*)(bias + lane128*4);
            v.x += bv.x; v.y += bv.y; v.z += bv.z; v.w += bv.w;
        }
        float m = fmaxf(fmaxf(v.x, v.y), fmaxf(v.z, v.w));
#pragma unroll
        for (int o = 16; o; o >>= 1) m = fmaxf(m, __shfl_xor_sync(0xffffffffu, m, o));
        __shared__ float sm[8];
        if ((t & 31) == 0) sm[t >> 5] = m;
        __syncthreads();
        const int wb = half*4;
        float M = fmaxf(fmaxf(sm[wb], sm[wb+1]), fmaxf(sm[wb+2], sm[wb+3]));
        float e0 = __expf(v.x - M), e1 = __expf(v.y - M);
        float e2 = __expf(v.z - M), e3 = __expf(v.w - M);
        uint2 h;
        h.x = pack_hi2(e0, e1);
        h.y = pack_hi2(e2, e3);
        ((uint2*)(oh + r*H2))[lane128] = h;
        if (lane128 == 0) om[r] = M;
    } else {
        const int bid2 = bid - 2304;        // 1024 blocks: db(1b) | b(3b) | js(6b)
        const int db = bid2 & 1;
        const int b  = (bid2 >> 1) & 7;
        const int js = bid2 >> 4;           // 0..63
        const int d  = db*256 + t;
        const float* e = enc + (long)b*TENC*H2 + (long)js*8*H2 + d;
        const float* p = ep  + (long)b*TENC*H2 + (long)js*8*H2 + d;
        float c = 0.f;
#pragma unroll
        for (int j = 0; j < 8; j++) c += p[(long)j*H2] * e[(long)j*H2];
        partC[((long)b*64 + js)*H2 + d] = c;
        if (js == 0) {
            float s = 0.f;
#pragma unroll
            for (int q = 0; q < 16; q++) s += partS[((long)b*16 + q)*H2 + d];
            Senc[(long)b*H2 + d] = s;
        }
    }
}

// ---------------------------------------------------------------------------
// 32x32 batched HMMA GEMM, K-chunk 64, 4-stage cp.async ring, 128 threads.
// Grid (16, 2, 8) = 256 CTAs. C = A*B^T per batch (bz), K=512.
// EPI==1: A,B single-bf16 -> 1 MMA term; 2 smem arrays.
//         v = mrow[gr] + mcol[bz*512+c] + log(acc) -> hi/lo bf16 out
// EPI==2: A hi/lo, B hi/lo -> 3 MMA terms; 4 smem arrays.
//         out = (dp+bias)*Senc + Cc(smem) - acc    -> fp32 out
// ---------------------------------------------------------------------------
#define APITCH  144                 // bytes per 64-col bf16 row (9x16B, odd)
#define A32ARR  (32*APITCH)         // 4608 per array
#define SMEM64_1 (4*(2*A32ARR))     // 36864
#define SMEM64_2 (4*(4*A32ARR))     // 73728

template<int EPI>
__global__ void __launch_bounds__(128) mma64(
    const __nv_bfloat16* __restrict__ Ahi, const __nv_bfloat16* __restrict__ Alo, long sA,
    const __nv_bfloat16* __restrict__ Bhi, const __nv_bfloat16* __restrict__ Blo, long sB,
    const float* __restrict__ mrow, const float* __restrict__ mcol,
    __nv_bfloat16* __restrict__ oHi, __nv_bfloat16* __restrict__ oLo,
    const float* __restrict__ dp, const float* __restrict__ bias,
    const float* __restrict__ Senc, const float* __restrict__ partC,
    float* __restrict__ out)
{
    constexpr int ARRS  = (EPI == 1) ? 2 : 4;
    constexpr int MO_AHI = 0;
    constexpr int MO_ALO = A32ARR;                       // EPI2 only
    constexpr int MO_BHI = ((EPI == 1) ? 1 : 2) * A32ARR;
    constexpr int MO_BLO = MO_BHI + A32ARR;              // EPI2 only
    constexpr int BUFSZ  = ARRS * A32ARR;

    extern __shared__ char smem[];
    __shared__ float sCc4[4][32];
    __shared__ float sCc[32];
    const uint32_t sb = smem_to_u32(smem);
    const int tid  = threadIdx.x;
    const int lane = tid & 31, wid = tid >> 5;
    const int warp_m = wid & 1, warp_n = wid >> 1;   // 2 x 2, warp tile 16x16
    const int bz = blockIdx.z;
    const int m0 = blockIdx.y * 32;
    const int n0 = blockIdx.x * 32;

    const __nv_bfloat16* Ah = Ahi + (long)bz*sA + (long)m0*H2;
    const __nv_bfloat16* Al = (EPI == 2) ? (Alo + (long)bz*sA + (long)m0*H2) : nullptr;
    const __nv_bfloat16* Bh = Bhi + (long)bz*sB;
    const __nv_bfloat16* Bl = (EPI == 2) ? (Blo + (long)bz*sB) : nullptr;

    // loads: 32 rows x 128B per array per chunk; thread -> row=tid>>2, 2x16B
    const int rowA = tid >> 2, cc = tid & 3;
    const long gA = (long)rowA*H2 + cc*8;            // + kc*64 (+32 for 2nd)
    const long gB = (long)(n0 + rowA)*H2 + cc*8;
    const uint32_t sOff  = rowA*APITCH + cc*16;
    const uint32_t sOff2 = sOff + 64;

    const int lrow = lane & 15;
    const int lk   = (lane >> 4) * 8;
    const uint32_t aOff = (uint32_t)(((warp_m*16 + lrow)*72 + lk)*2);
    const uint32_t bOff = (uint32_t)(((warp_n*16 + lrow)*72 + lk)*2);

    float acc[2][4];
#pragma unroll
    for (int n = 0; n < 2; n++)
#pragma unroll
        for (int q = 0; q < 4; q++) acc[n][q] = 0.f;

    // prologue: issue chunks 0,1,2 into stages 0,1,2
#pragma unroll
    for (int pc = 0; pc < 3; pc++) {
        const uint32_t db = sb + pc*BUFSZ;
        const long gk = (long)pc*64;
        CP_ASYNC16(db + MO_AHI + sOff,  (const char*)(Ah + gA + gk));
        CP_ASYNC16(db + MO_AHI + sOff2, (const char*)(Ah + gA + gk + 32));
        if (EPI == 2) {
            CP_ASYNC16(db + MO_ALO + sOff,  (const char*)(Al + gA + gk));
            CP_ASYNC16(db + MO_ALO + sOff2, (const char*)(Al + gA + gk + 32));
        }
        CP_ASYNC16(db + MO_BHI + sOff,  (const char*)(Bh + gB + gk));
        CP_ASYNC16(db + MO_BHI + sOff2, (const char*)(Bh + gB + gk + 32));
        if (EPI == 2) {
            CP_ASYNC16(db + MO_BLO + sOff,  (const char*)(Bl + gB + gk));
            CP_ASYNC16(db + MO_BLO + sOff2, (const char*)(Bl + gB + gk + 32));
        }
        CP_COMMIT();
    }
    // overlap: partial Cc sums (4 threads per column, 16 partials each)
    if (EPI == 2) {
        const int c = tid & 31, q = tid >> 5;
        float s = 0.f;
#pragma unroll
        for (int js = 0; js < 16; js++)
            s += partC[((long)bz*64 + q*16 + js)*H2 + n0 + c];
        sCc4[q][c] = s;
    }
    __syncthreads();
    if (EPI == 2 && tid < 32)
        sCc[tid] = sCc4[0][tid] + sCc4[1][tid] + sCc4[2][tid] + sCc4[3][tid];

    for (int kc = 0; kc < 8; kc++) {
        if (kc < 6)       { CP_WAIT2(); }
        else if (kc == 6) { CP_WAIT1(); }
        else              { CP_WAIT0(); }
        __syncthreads();
        if (kc + 3 < 8) {
            const uint32_t db = sb + ((kc + 3) & 3)*BUFSZ;
            const long gk = (long)(kc + 3)*64;
            CP_ASYNC16(db + MO_AHI + sOff,  (const char*)(Ah + gA + gk));
            CP_ASYNC16(db + MO_AHI + sOff2, (const char*)(Ah + gA + gk + 32));
            if (EPI == 2) {
                CP_ASYNC16(db + MO_ALO + sOff,  (const char*)(Al + gA + gk));
                CP_ASYNC16(db + MO_ALO + sOff2, (const char*)(Al + gA + gk + 32));
            }
            CP_ASYNC16(db + MO_BHI + sOff,  (const char*)(Bh + gB + gk));
            CP_ASYNC16(db + MO_BHI + sOff2, (const char*)(Bh + gB + gk + 32));
            if (EPI == 2) {
                CP_ASYNC16(db + MO_BLO + sOff,  (const char*)(Bl + gB + gk));
                CP_ASYNC16(db + MO_BLO + sOff2, (const char*)(Bl + gB + gk + 32));
            }
            CP_COMMIT();
        }
        const uint32_t cb = sb + (kc & 3)*BUFSZ;
#pragma unroll
        for (int kk = 0; kk < 4; kk++) {
            const uint32_t ko = kk*32;   // 16 cols * 2B
            uint32_t ah[4];
            LDSM_X4(ah[0], ah[1], ah[2], ah[3], cb + MO_AHI + aOff + ko);
            uint32_t bh0, bh1, bh2, bh3;
            LDSM_X4(bh0, bh1, bh2, bh3, cb + MO_BHI + bOff + ko);
            MMA_BF16(acc[0], ah, bh0, bh2);
            MMA_BF16(acc[1], ah, bh1, bh3);
            if (EPI == 2) {
                uint32_t bl0, bl1, bl2, bl3, al[4];
                LDSM_X4(bl0, bl1, bl2, bl3, cb + MO_BLO + bOff + ko);
                LDSM_X4(al[0], al[1], al[2], al[3], cb + MO_ALO + aOff + ko);
                MMA_BF16(acc[0], ah, bl0, bl2);
                MMA_BF16(acc[1], ah, bl1, bl3);
                MMA_BF16(acc[0], al, bh0, bh2);
                MMA_BF16(acc[1], al, bh1, bh3);
            }
        }
    }

    const int rbase = warp_m*16 + (lane >> 2);
    const int cbase = n0 + warp_n*16 + (lane & 3)*2;
#pragma unroll
    for (int n = 0; n < 2; n++) {
#pragma unroll
        for (int h = 0; h < 2; h++) {
            const int r  = rbase + h*8;
            const int gr = bz*TDEC + m0 + r;
            const int c  = cbase + n*8;
            const float a0 = acc[n][2*h], a1 = acc[n][2*h+1];
            if (EPI == 1) {
                float mr = mrow[gr];
                float v0 = mr + mcol[(long)bz*TENC + c]     + __logf(a0);
                float v1 = mr + mcol[(long)bz*TENC + c + 1] + __logf(a1);
                uint32_t hh, ll;
                split2(v0, v1, hh, ll);
                *(uint32_t*)(oHi + (long)gr*TENC + c) = hh;
                *(uint32_t*)(oLo + (long)gr*TENC + c) = ll;
            } else {
                const long ib = (long)bz*H2 + c;
                float o0 = (dp[(long)gr*H2 + c]   + bias[c])   * Senc[ib]   + sCc[c - n0]     - a0;
                float o1 = (dp[(long)gr*H2 + c+1] + bias[c+1]) * Senc[ib+1] + sCc[c - n0 + 1] - a1;
                float2 ov; ov.x = o0; ov.y = o1;
                *(float2*)(out + (long)gr*H2 + c) = ov;
            }
        }
    }
}

// ---------------------------------------------------------------------------
extern "C" void kernel_launch(void* const* d_in, const int* in_sizes, int n_in,
                              void* d_out, int out_size)
{
    const float* enc  = (const float*)d_in[0];
    const float* dec  = (const float*)d_in[1];
    const float* W    = (const float*)d_in[2];
    const float* bias = (const float*)d_in[3];
    float* out = (float*)d_out;

    float *dp, *ep, *mdp, *mep, *Senc, *pS, *pC;
    __nv_bfloat16 *ehi, *elo, *ethi, *etlo, *dhi, *dlo, *wehi, *welo, *wdhi, *wdlo;
    __nv_bfloat16 *Ahi, *Ehi, *Lhi, *Llo;
    cudaGetSymbolAddress((void**)&dp,   g_dp);
    cudaGetSymbolAddress((void**)&ep,   g_ep);
    cudaGetSymbolAddress((void**)&mdp,  g_mdp);
    cudaGetSymbolAddress((void**)&mep,  g_mep);
    cudaGetSymbolAddress((void**)&Senc, g_Senc);
    cudaGetSymbolAddress((void**)&pS,   g_partS);
    cudaGetSymbolAddress((void**)&pC,   g_partC);
    cudaGetSymbolAddress((void**)&ehi,  g_enc_hi);
    cudaGetSymbolAddress((void**)&elo,  g_enc_lo);
    cudaGetSymbolAddress((void**)&ethi, g_encT_hi);
    cudaGetSymbolAddress((void**)&etlo, g_encT_lo);
    cudaGetSymbolAddress((void**)&dhi,  g_dec_hi);
    cudaGetSymbolAddress((void**)&dlo,  g_dec_lo);
    cudaGetSymbolAddress((void**)&wehi, g_We_hi);
    cudaGetSymbolAddress((void**)&welo, g_We_lo);
    cudaGetSymbolAddress((void**)&wdhi, g_Wd_hi);
    cudaGetSymbolAddress((void**)&wdlo, g_Wd_lo);
    cudaGetSymbolAddress((void**)&Ahi,  g_Ahi);
    cudaGetSymbolAddress((void**)&Ehi,  g_Ehi);
    cudaGetSymbolAddress((void**)&Lhi,  g_Lhi);
    cudaGetSymbolAddress((void**)&Llo,  g_Llo);

    cudaFuncSetAttribute(gemm_mma_dual, cudaFuncAttributeMaxDynamicSharedMemorySize, MMA_SMEM);
    cudaFuncSetAttribute(mma64<1>, cudaFuncAttributeMaxDynamicSharedMemorySize, SMEM64_1);
    cudaFuncSetAttribute(mma64<2>, cudaFuncAttributeMaxDynamicSharedMemorySize, SMEM64_2);

    // 0: all conversions + encT + partS
    conv_all<<<2816, 256>>>(enc, dec, W, ehi, elo, ethi, etlo,
                            dhi, dlo, wdhi, wdlo, wehi, welo, pS);
    // 1: ep + dp GEMMs
    gemm_mma_dual<<<dim3(4, 36), 256, MMA_SMEM>>>(
        ehi, elo, wehi, welo, ep, dhi, dlo, wdhi, wdlo, dp);
    // 2: rowmax+exp (E hi, A hi) + colreduceC + Senc finalize
    fused_mid<<<3328, 256>>>(ep, dp, enc, bias, Ehi, mep,
                             Ahi, mdp, pC, pS, Senc);
    // 3: L = mdp + mep + log(A @ E^T) -> hi/lo  (256 CTAs, 1-term)
    mma64<1><<<dim3(16, 2, NB), 128, SMEM64_1>>>(
        Ahi, nullptr, (long)TDEC*H2, Ehi, nullptr, (long)TENC*H2,
        mdp, mep, Lhi, Llo, nullptr, nullptr, nullptr, nullptr, nullptr);
    // 4: context = (dp+bias)*Senc + Cc - L @ enc  (256 CTAs, 3-term)
    mma64<2><<<dim3(16, 2, NB), 128, SMEM64_2>>>(
        Lhi, Llo, (long)TDEC*TENC, ethi, etlo, (long)H2*TENC,
        nullptr, nullptr, nullptr, nullptr, dp, bias, Senc, pC, out);
}